// round 15
// baseline (speedup 1.0000x reference)
#include <cuda_runtime.h>
#include <cuda_fp16.h>
#include <cstdint>
#include <math.h>

#define DIM 384
#define HEADS 12
#define HEAD_DIM 32
#define NTOK 131072          // 32*64*64 tokens
#define QKV_N 1152
#define MLP_HIDDEN 1536
#define ATT_SCALE 0.17677669529663687f   // 32^-0.5

// ---------------- scratch (static device globals; no allocations) -------------
__device__ __half g_xt[NTOK * DIM];           // token-major input (shortcut, half)
__device__ __half g_xw[NTOK * DIM];           // LN output (GEMM A input)
__device__ __half g_qkv[NTOK * QKV_N];        // qkv projections (half)
__device__ __half g_attout[NTOK * DIM];       // attention output (GEMM A input)
__device__ __half g_x1[NTOK * DIM];           // post-attention residual (half)
__device__ __half g_h[NTOK * MLP_HIDDEN];     // MLP hidden (GEMM A input)
__device__ float  g_biasT[HEADS * 225];       // rel_bias transposed per head
// transposed (N,K) weights in fp16
__device__ __half g_wt_qkv[QKV_N * DIM];
__device__ __half g_wt_proj[DIM * DIM];
__device__ __half g_wt_fc1[MLP_HIDDEN * DIM];
__device__ __half g_wt_fc2[DIM * MLP_HIDDEN];

// ---------------- mma / ldmatrix helpers --------------------------------------
#define LDSM_X4(r0, r1, r2, r3, addr) \
    asm volatile("ldmatrix.sync.aligned.m8n8.x4.shared.b16 {%0,%1,%2,%3}, [%4];" \
                 : "=r"(r0), "=r"(r1), "=r"(r2), "=r"(r3) : "r"(addr))
#define LDSM_X4_T(r0, r1, r2, r3, addr) \
    asm volatile("ldmatrix.sync.aligned.m8n8.x4.trans.shared.b16 {%0,%1,%2,%3}, [%4];" \
                 : "=r"(r0), "=r"(r1), "=r"(r2), "=r"(r3) : "r"(addr))
#define MMA16816(d, a0, a1, a2, a3, b0, b1) \
    asm volatile("mma.sync.aligned.m16n8k16.row.col.f32.f16.f16.f32 " \
                 "{%0,%1,%2,%3}, {%4,%5,%6,%7}, {%8,%9}, {%0,%1,%2,%3};" \
                 : "+f"((d)[0]), "+f"((d)[1]), "+f"((d)[2]), "+f"((d)[3]) \
                 : "r"(a0), "r"(a1), "r"(a2), "r"(a3), "r"(b0), "r"(b1))

// fast GELU: 0.5x(1+tanh(sqrt(2/pi)(x+0.044715x^3))) with MUFU.TANH
__device__ __forceinline__ float gelu_fast(float u) {
    float t;
    float a = 0.7978845608028654f * (u + 0.044715f * u * u * u);
    asm("tanh.approx.f32 %0, %1;" : "=f"(t) : "f"(a));
    return 0.5f * u * (1.0f + t);
}

// ---------------- weight transposes + bias transpose, ONE launch --------------
__global__ void transpose_w4(const float* __restrict__ qkv_w, const float* __restrict__ proj_w,
                             const float* __restrict__ fc1_w, const float* __restrict__ fc2_w,
                             const float* __restrict__ rel_bias,
                             __half* __restrict__ wt_qkv, __half* __restrict__ wt_proj,
                             __half* __restrict__ wt_fc1, __half* __restrict__ wt_fc2,
                             float* __restrict__ biasT) {
    __shared__ float tile[32][33];
    int z = blockIdx.z;
    if (z == 4) {   // rel_bias transpose [225][12] -> [12][225]
        if (blockIdx.x == 0 && blockIdx.y == 0) {
            int i = threadIdx.y * 32 + threadIdx.x;
            for (; i < 225 * HEADS; i += 256) {
                int idx = i / HEADS, h = i - idx * HEADS;
                biasT[h * 225 + idx] = rel_bias[i];
            }
        }
        return;
    }
    const float* W;
    __half* Wt;
    int K, N;
    if (z == 0)      { W = qkv_w;  Wt = wt_qkv;  K = DIM;        N = QKV_N; }
    else if (z == 1) { W = proj_w; Wt = wt_proj; K = DIM;        N = DIM; }
    else if (z == 2) { W = fc1_w;  Wt = wt_fc1;  K = DIM;        N = MLP_HIDDEN; }
    else             { W = fc2_w;  Wt = wt_fc2;  K = MLP_HIDDEN; N = DIM; }
    int n0 = blockIdx.x * 32;
    int k0 = blockIdx.y * 32;
    if (n0 >= N || k0 >= K) return;
    int tx = threadIdx.x, ty = threadIdx.y;
#pragma unroll
    for (int i = 0; i < 32; i += 8)
        tile[ty + i][tx] = W[(size_t)(k0 + ty + i) * N + n0 + tx];
    __syncthreads();
#pragma unroll
    for (int i = 0; i < 32; i += 8)
        Wt[(size_t)(n0 + ty + i) * K + k0 + tx] = __float2half_rn(tile[tx][ty + i]);
}

// ---------------- fused BCHW->token transpose + LN1 + shift + window scatter --
__global__ void fuse_in_ln(const float* __restrict__ x,
                           const float* __restrict__ gamma,
                           const float* __restrict__ beta,
                           __half* __restrict__ xt, __half* __restrict__ xw) {
    extern __shared__ float tile[];   // [384][33]
    int b = blockIdx.y;
    int p0 = blockIdx.x * 32;
    const float* xb = x + (size_t)b * DIM * 4096;
    int tx = threadIdx.x & 31;
    int ty = threadIdx.x >> 5;   // warp id, 8 warps

    for (int c = ty; c < DIM; c += 8)
        tile[c * 33 + tx] = xb[(size_t)c * 4096 + p0 + tx];
    __syncthreads();

    int lane = tx;
#pragma unroll
    for (int ti = 0; ti < 4; ti++) {
        int t = ty * 4 + ti;                 // 0..31
        int hw = p0 + t;
        float vals[12];
        float s = 0.f;
#pragma unroll
        for (int k = 0; k < 12; k++) {
            vals[k] = tile[(lane + k * 32) * 33 + t];
            s += vals[k];
        }
#pragma unroll
        for (int o = 16; o; o >>= 1) s += __shfl_xor_sync(0xffffffffu, s, o);
        float mu = s * (1.f / 384.f);
        float vv = 0.f;
#pragma unroll
        for (int k = 0; k < 12; k++) { float d = vals[k] - mu; vv += d * d; }
#pragma unroll
        for (int o = 16; o; o >>= 1) vv += __shfl_xor_sync(0xffffffffu, vv, o);
        float rstd = rsqrtf(vv * (1.f / 384.f) + 1e-5f);

        __half* xtr = xt + ((size_t)b * 4096 + hw) * DIM;
        int hs = hw >> 6, ws = hw & 63;
        int h = (hs + 60) & 63;   // unshift
        int w = (ws + 60) & 63;
        int drow = b * 4096 + ((h >> 3) * 8 + (w >> 3)) * 64 + ((h & 7) * 8 + (w & 7));
        __half* xwr = xw + (size_t)drow * DIM;
#pragma unroll
        for (int k = 0; k < 12; k++) {
            int c = lane + k * 32;
            xtr[c] = __float2half_rn(vals[k]);
            xwr[c] = __float2half_rn((vals[k] - mu) * rstd * gamma[c] + beta[c]);
        }
    }
}

// ---------------- LayerNorm (token-order half in/out, vectorized) -------------
__global__ void ln_kernel(const __half* __restrict__ src,
                          const float* __restrict__ gamma,
                          const float* __restrict__ beta,
                          __half* __restrict__ dst) {
    int warp = (blockIdx.x * blockDim.x + threadIdx.x) >> 5;
    int lane = threadIdx.x & 31;
    if (warp >= NTOK) return;

    const __half2* row2 = (const __half2*)(src + (size_t)warp * DIM);
    float2 v[6];
    float s = 0.f;
#pragma unroll
    for (int k = 0; k < 6; k++) {
        v[k] = __half22float2(row2[lane + k * 32]);
        s += v[k].x + v[k].y;
    }
#pragma unroll
    for (int o = 16; o; o >>= 1) s += __shfl_xor_sync(0xffffffffu, s, o);
    float mu = s * (1.f / 384.f);
    float vv = 0.f;
#pragma unroll
    for (int k = 0; k < 6; k++) {
        float d0 = v[k].x - mu, d1 = v[k].y - mu;
        vv += d0 * d0 + d1 * d1;
    }
#pragma unroll
    for (int o = 16; o; o >>= 1) vv += __shfl_xor_sync(0xffffffffu, vv, o);
    float rstd = rsqrtf(vv * (1.f / 384.f) + 1e-5f);

    __half2* orow = (__half2*)(dst + (size_t)warp * DIM);
#pragma unroll
    for (int k = 0; k < 6; k++) {
        int c = (lane + k * 32) * 2;
        float o0 = (v[k].x - mu) * rstd * gamma[c] + beta[c];
        float o1 = (v[k].y - mu) * rstd * gamma[c + 1] + beta[c + 1];
        orow[lane + k * 32] = __floats2half2_rn(o0, o1);
    }
}

// ---------------- fused windowed attention (fp16 mma) ------------------------
__device__ __forceinline__ int region64(int v) { return v < 56 ? 0 : (v < 60 ? 1 : 2); }

__device__ __forceinline__ unsigned pkh2(float a, float b) {
    __half2 h = __floats2half2_rn(a, b);
    return *(unsigned*)&h;
}

#define ASTRIDE 40   // halfs per row: conflict-free for ldmatrix

__global__ __launch_bounds__(128) void attn_mma(const __half* __restrict__ qkv,
                                                const float* __restrict__ biasT,
                                                __half* __restrict__ out) {
    __shared__ __half Qs[64 * ASTRIDE];
    __shared__ __half Ks[64 * ASTRIDE];
    __shared__ __half Vs[64 * ASTRIDE];
    __shared__ float sbias[225];

    int blk = blockIdx.x;
    int win = blk / HEADS;
    int head = blk - win * HEADS;
    int tid = threadIdx.x;
    int lane = tid & 31, warp = tid >> 5;
    int grp = lane >> 2, lig = lane & 3;

    if (tid < 113) {
        sbias[tid] = biasT[head * 225 + tid];
        if (tid + 113 < 225) sbias[tid + 113] = biasT[head * 225 + tid + 113];
    }

    {   // stage Q,K,V via cp.async (16B each, all aligned)
        int n = tid >> 1;
        int c0 = (tid & 1) << 4;
        const __half* rowp = qkv + (size_t)(win * 64 + n) * QKV_N + head * HEAD_DIM + c0;
        unsigned q0 = (unsigned)__cvta_generic_to_shared(&Qs[n * ASTRIDE + c0]);
        unsigned k0 = (unsigned)__cvta_generic_to_shared(&Ks[n * ASTRIDE + c0]);
        unsigned v0 = (unsigned)__cvta_generic_to_shared(&Vs[n * ASTRIDE + c0]);
        asm volatile("cp.async.cg.shared.global [%0], [%1], 16;\n" :: "r"(q0), "l"(rowp));
        asm volatile("cp.async.cg.shared.global [%0], [%1], 16;\n" :: "r"(q0 + 16), "l"(rowp + 8));
        asm volatile("cp.async.cg.shared.global [%0], [%1], 16;\n" :: "r"(k0), "l"(rowp + DIM));
        asm volatile("cp.async.cg.shared.global [%0], [%1], 16;\n" :: "r"(k0 + 16), "l"(rowp + DIM + 8));
        asm volatile("cp.async.cg.shared.global [%0], [%1], 16;\n" :: "r"(v0), "l"(rowp + 2 * DIM));
        asm volatile("cp.async.cg.shared.global [%0], [%1], 16;\n" :: "r"(v0 + 16), "l"(rowp + 2 * DIM + 8));
        asm volatile("cp.async.commit_group;\n");
    }
    asm volatile("cp.async.wait_group 0;\n" ::: "memory");
    __syncthreads();

    const unsigned qb = (unsigned)__cvta_generic_to_shared(Qs);
    const unsigned kb = (unsigned)__cvta_generic_to_shared(Ks);
    const unsigned vb = (unsigned)__cvta_generic_to_shared(Vs);
    const int g = lane >> 3, j = lane & 7;

    unsigned qa[2][4];
#pragma unroll
    for (int kc = 0; kc < 2; kc++) {
        int row = warp * 16 + (g & 1) * 8 + j;
        int col = kc * 16 + (g >> 1) * 8;
        LDSM_X4(qa[kc][0], qa[kc][1], qa[kc][2], qa[kc][3],
                qb + (unsigned)((row * ASTRIDE + col) * 2));
    }

    float sacc[8][4];
#pragma unroll
    for (int nt = 0; nt < 8; nt++)
#pragma unroll
        for (int i = 0; i < 4; i++) sacc[nt][i] = 0.f;

#pragma unroll
    for (int kc = 0; kc < 2; kc++) {
#pragma unroll
        for (int p = 0; p < 4; p++) {
            unsigned kf[4];
            int row = p * 16 + (g >> 1) * 8 + j;
            int col = kc * 16 + (g & 1) * 8;
            LDSM_X4(kf[0], kf[1], kf[2], kf[3],
                    kb + (unsigned)((row * ASTRIDE + col) * 2));
            MMA16816(sacc[2 * p],     qa[kc][0], qa[kc][1], qa[kc][2], qa[kc][3], kf[0], kf[1]);
            MMA16816(sacc[2 * p + 1], qa[kc][0], qa[kc][1], qa[kc][2], qa[kc][3], kf[2], kf[3]);
        }
    }

    int win_img = win & 63;
    int wy = win_img >> 3, wx = win_img & 7;
    bool masked = (wy == 7) || (wx == 7);
    int r_lo = warp * 16 + grp, r_hi = r_lo + 8;
    int ry_lo = r_lo >> 3, rx = r_lo & 7;
    int ry_hi = r_hi >> 3;
    int reg_lo = 0, reg_hi = 0;
    if (masked) {
        reg_lo = region64(wy * 8 + ry_lo) * 3 + region64(wx * 8 + rx);
        reg_hi = region64(wy * 8 + ry_hi) * 3 + region64(wx * 8 + rx);
    }

    float mx_lo = -1e30f, mx_hi = -1e30f;
#pragma unroll
    for (int nt = 0; nt < 8; nt++) {
#pragma unroll
        for (int jj = 0; jj < 2; jj++) {
            int c = nt * 8 + 2 * lig + jj;
            int cy = c >> 3, cx = c & 7;
            float blo = sbias[(ry_lo - cy + 7) * 15 + (rx - cx + 7)];
            float bhi = sbias[(ry_hi - cy + 7) * 15 + (rx - cx + 7)];
            float mlo = 0.f, mhi = 0.f;
            if (masked) {
                int regc = region64(wy * 8 + cy) * 3 + region64(wx * 8 + cx);
                mlo = (reg_lo != regc) ? -10.f : 0.f;
                mhi = (reg_hi != regc) ? -10.f : 0.f;
            }
            float vlo = sacc[nt][jj] * ATT_SCALE + blo + mlo;
            float vhi = sacc[nt][2 + jj] * ATT_SCALE + bhi + mhi;
            sacc[nt][jj] = vlo;
            sacc[nt][2 + jj] = vhi;
            mx_lo = fmaxf(mx_lo, vlo);
            mx_hi = fmaxf(mx_hi, vhi);
        }
    }
    mx_lo = fmaxf(mx_lo, __shfl_xor_sync(0xffffffffu, mx_lo, 1));
    mx_lo = fmaxf(mx_lo, __shfl_xor_sync(0xffffffffu, mx_lo, 2));
    mx_hi = fmaxf(mx_hi, __shfl_xor_sync(0xffffffffu, mx_hi, 1));
    mx_hi = fmaxf(mx_hi, __shfl_xor_sync(0xffffffffu, mx_hi, 2));

    float sm_lo = 0.f, sm_hi = 0.f;
#pragma unroll
    for (int nt = 0; nt < 8; nt++) {
#pragma unroll
        for (int jj = 0; jj < 2; jj++) {
            float elo = __expf(sacc[nt][jj] - mx_lo);
            float ehi = __expf(sacc[nt][2 + jj] - mx_hi);
            sacc[nt][jj] = elo;
            sacc[nt][2 + jj] = ehi;
            sm_lo += elo;
            sm_hi += ehi;
        }
    }
    sm_lo += __shfl_xor_sync(0xffffffffu, sm_lo, 1);
    sm_lo += __shfl_xor_sync(0xffffffffu, sm_lo, 2);
    sm_hi += __shfl_xor_sync(0xffffffffu, sm_hi, 1);
    sm_hi += __shfl_xor_sync(0xffffffffu, sm_hi, 2);
    float inv_lo = 1.f / sm_lo, inv_hi = 1.f / sm_hi;

    float oacc[4][4];
#pragma unroll
    for (int nt = 0; nt < 4; nt++)
#pragma unroll
        for (int i = 0; i < 4; i++) oacc[nt][i] = 0.f;

#pragma unroll
    for (int kc = 0; kc < 4; kc++) {
        unsigned pa[4];
        pa[0] = pkh2(sacc[2 * kc][0] * inv_lo,     sacc[2 * kc][1] * inv_lo);
        pa[1] = pkh2(sacc[2 * kc][2] * inv_hi,     sacc[2 * kc][3] * inv_hi);
        pa[2] = pkh2(sacc[2 * kc + 1][0] * inv_lo, sacc[2 * kc + 1][1] * inv_lo);
        pa[3] = pkh2(sacc[2 * kc + 1][2] * inv_hi, sacc[2 * kc + 1][3] * inv_hi);
#pragma unroll
        for (int q = 0; q < 2; q++) {
            unsigned vf[4];
            int row = kc * 16 + (g & 1) * 8 + j;
            int col = q * 16 + (g >> 1) * 8;
            LDSM_X4_T(vf[0], vf[1], vf[2], vf[3],
                      vb + (unsigned)((row * ASTRIDE + col) * 2));
            MMA16816(oacc[2 * q],     pa[0], pa[1], pa[2], pa[3], vf[0], vf[1]);
            MMA16816(oacc[2 * q + 1], pa[0], pa[1], pa[2], pa[3], vf[2], vf[3]);
        }
    }

#pragma unroll
    for (int nt = 0; nt < 4; nt++) {
        int col = head * HEAD_DIM + nt * 8 + 2 * lig;
        __half2 lo = __floats2half2_rn(oacc[nt][0], oacc[nt][1]);
        __half2 hi = __floats2half2_rn(oacc[nt][2], oacc[nt][3]);
        *(__half2*)&out[(size_t)(win * 64 + r_lo) * DIM + col] = lo;
        *(__half2*)&out[(size_t)(win * 64 + r_hi) * DIM + col] = hi;
    }
}

// ================= fp16 tensor-core GEMM (m16n8k16 mma.sync) =================
// MODE 0: half out. MODE 1: GELU, half out.
// MODE 3: window-reverse+unshift + residual(half), half out (token order).
// MODE 4: +res(half), write BCHW (transposed, dual smem staging), float out.
#define BKH 64
#define SA 72
#define SB 72
#define STAGES 3
#define HG_SMEM (STAGES * 128 * (SA + SB) * 2)

template <int MODE>
__global__ __launch_bounds__(256, 2) void hgemm(const __half* __restrict__ A,
                                                const __half* __restrict__ Bt,
                                                const float* __restrict__ bias,
                                                const __half* __restrict__ res,
                                                void* __restrict__ Cout,
                                                int M, int N, int K) {
    extern __shared__ __half dsm[];
    __half* Asb = dsm;                          // STAGES * 128*SA
    __half* Bsb = dsm + STAGES * 128 * SA;      // STAGES * 128*SB

    const int tid = threadIdx.x;
    const int lane = tid & 31;
    const int wid = tid >> 5;
    const int grp = lane >> 2;
    const int lig = lane & 3;
    const int g = lane >> 3;
    const int j = lane & 7;
    const int wm = wid & 3;
    const int wn = wid >> 2;
    const int bm = blockIdx.y * 128;
    const int bn = blockIdx.x * 128;

    const int l_r = tid >> 3;           // 0..31
    const int l_c = (tid & 7) << 3;     // 0,8,...,56 halfs

    float acc[2][8][4];
#pragma unroll
    for (int mt = 0; mt < 2; mt++)
#pragma unroll
        for (int nt = 0; nt < 8; nt++)
#pragma unroll
            for (int i = 0; i < 4; i++) acc[mt][nt][i] = 0.f;

    const int T = K / BKH;

    auto issue = [&](int t) {
        if (t < T) {
            int kt = t * BKH;
            int buf = t % STAGES;
            __half* Ad = Asb + buf * 128 * SA;
            __half* Bd = Bsb + buf * 128 * SB;
#pragma unroll
            for (int i = 0; i < 4; i++) {
                int r = l_r + 32 * i;
                const __half* gp = A + (size_t)(bm + r) * K + kt + l_c;
                unsigned s = (unsigned)__cvta_generic_to_shared(&Ad[r * SA + l_c]);
                asm volatile("cp.async.cg.shared.global [%0], [%1], 16;\n" :: "r"(s), "l"(gp));
            }
#pragma unroll
            for (int i = 0; i < 4; i++) {
                int r = l_r + 32 * i;
                const __half* gp = Bt + (size_t)(bn + r) * K + kt + l_c;
                unsigned s = (unsigned)__cvta_generic_to_shared(&Bd[r * SB + l_c]);
                asm volatile("cp.async.cg.shared.global [%0], [%1], 16;\n" :: "r"(s), "l"(gp));
            }
        }
        asm volatile("cp.async.commit_group;\n");
    };

    issue(0);
    issue(1);

    for (int t = 0; t < T; t++) {
        asm volatile("cp.async.wait_group 1;\n" ::: "memory");
        __syncthreads();

        int buf = t % STAGES;
        const unsigned abx = (unsigned)__cvta_generic_to_shared(Asb + buf * 128 * SA);
        const unsigned bbx = (unsigned)__cvta_generic_to_shared(Bsb + buf * 128 * SB);

        unsigned af[2][4], bf[4][4];
        auto ldfrag = [&](int kk) {
            int colA = kk * 16 + (g >> 1) * 8;
#pragma unroll
            for (int mt = 0; mt < 2; mt++) {
                int row = wm * 32 + mt * 16 + (g & 1) * 8 + j;
                LDSM_X4(af[mt][0], af[mt][1], af[mt][2], af[mt][3],
                        abx + (unsigned)((row * SA + colA) * 2));
            }
#pragma unroll
            for (int p = 0; p < 4; p++) {
                int row = wn * 64 + p * 16 + (g & 1) * 8 + j;
                LDSM_X4(bf[p][0], bf[p][1], bf[p][2], bf[p][3],
                        bbx + (unsigned)((row * SB + colA) * 2));
            }
        };

        ldfrag(0);
        issue(t + 2);

#pragma unroll
        for (int kk = 0; kk < 4; kk++) {
#pragma unroll
            for (int mt = 0; mt < 2; mt++)
#pragma unroll
                for (int p = 0; p < 4; p++) {
                    MMA16816(acc[mt][2 * p],     af[mt][0], af[mt][1], af[mt][2], af[mt][3],
                             bf[p][0], bf[p][2]);
                    MMA16816(acc[mt][2 * p + 1], af[mt][0], af[mt][1], af[mt][2], af[mt][3],
                             bf[p][1], bf[p][3]);
                }
            if (kk < 3) ldfrag(kk + 1);
        }
    }
    __syncthreads();

    if (MODE == 4) {
        // FC2: bias + residual, then transposed write to BCHW via DUAL smem staging.
        // Pass p (0,1): warps wn stage chunk c = p + 2*wn into buffer wn; then all
        // threads write both chunks coalesced to BCHW.
        float* st = reinterpret_cast<float*>(Asb);  // 2 buffers x 128x33 floats = 33.8KB
        int b = bm >> 12;
        int hw0 = bm & 4095;
        float* ybase = (float*)Cout + ((size_t)b * DIM + bn) * 4096 + hw0;
#pragma unroll
        for (int p = 0; p < 2; p++) {
            int c = p + 2 * wn;          // chunk this warp stages
            int nt0 = p * 4;             // warp-local n-tile base
            float* stb = st + wn * (128 * 33);
#pragma unroll
            for (int mt = 0; mt < 2; mt++)
#pragma unroll
                for (int hf = 0; hf < 2; hf++) {
                    int ml = wm * 32 + mt * 16 + grp + hf * 8;
                    const __half* rr = res + (size_t)(bm + ml) * DIM + bn + c * 32;
#pragma unroll
                    for (int q = 0; q < 4; q++) {
                        int nt = nt0 + q;
                        int nl = q * 8 + lig * 2;
                        int ng = bn + c * 32 + nl;
                        __half2 rv = *(const __half2*)(rr + nl);
                        stb[ml * 33 + nl]     = acc[mt][nt][hf * 2 + 0] + bias[ng] + __half2float(rv.x);
                        stb[ml * 33 + nl + 1] = acc[mt][nt][hf * 2 + 1] + bias[ng + 1] + __half2float(rv.y);
                    }
                }
            __syncthreads();
            {
                int nl = tid >> 3;
                int m0 = (tid & 7) << 4;
#pragma unroll
                for (int k = 0; k < 2; k++) {
                    int cg = p + 2 * k;
                    const float* sk = st + k * (128 * 33);
                    float* dst = ybase + (size_t)(cg * 32 + nl) * 4096 + m0;
#pragma unroll
                    for (int i = 0; i < 4; i++) {
                        float4 o;
                        o.x = sk[(m0 + 4 * i + 0) * 33 + nl];
                        o.y = sk[(m0 + 4 * i + 1) * 33 + nl];
                        o.z = sk[(m0 + 4 * i + 2) * 33 + nl];
                        o.w = sk[(m0 + 4 * i + 3) * 33 + nl];
                        *(float4*)(dst + 4 * i) = o;
                    }
                }
            }
            __syncthreads();
        }
        return;
    }

#pragma unroll
    for (int mt = 0; mt < 2; mt++) {
#pragma unroll
        for (int half_ = 0; half_ < 2; half_++) {
            int m = bm + wm * 32 + mt * 16 + grp + half_ * 8;
            size_t crow;
            size_t rrow = 0;
            if (MODE == 3) {
                int b = m >> 12, win = (m >> 6) & 63, pos = m & 63;
                int wy = win >> 3, wx = win & 7, iy = pos >> 3, ix = pos & 7;
                int h = (wy * 8 + iy + 4) & 63;
                int w = (wx * 8 + ix + 4) & 63;
                size_t tk = (size_t)b * 4096 + h * 64 + w;
                crow = tk * N;
                rrow = tk * DIM;
            } else {
                crow = (size_t)m * N;
            }
#pragma unroll
            for (int nt = 0; nt < 8; nt++) {
                int n = bn + wn * 64 + nt * 8 + lig * 2;
                float v0 = acc[mt][nt][half_ * 2 + 0] + bias[n];
                float v1 = acc[mt][nt][half_ * 2 + 1] + bias[n + 1];
                if (MODE == 0) {
                    *(__half2*)((__half*)Cout + crow + n) = __floats2half2_rn(v0, v1);
                } else if (MODE == 1) {
                    v0 = gelu_fast(v0);
                    v1 = gelu_fast(v1);
                    *(__half2*)((__half*)Cout + crow + n) = __floats2half2_rn(v0, v1);
                } else {  // MODE 3: + residual(half), half out
                    __half2 rv = *(const __half2*)(res + rrow + n);
                    v0 += __half2float(rv.x);
                    v1 += __half2float(rv.y);
                    *(__half2*)((__half*)Cout + crow + n) = __floats2half2_rn(v0, v1);
                }
            }
        }
    }
}

// ---------------- launcher -----------------------------------------------------
extern "C" void kernel_launch(void* const* d_in, const int* in_sizes, int n_in,
                              void* d_out, int out_size) {
    const float* x       = (const float*)d_in[0];
    const float* qkv_w   = (const float*)d_in[1];
    const float* qkv_b   = (const float*)d_in[2];
    const float* proj_w  = (const float*)d_in[3];
    const float* proj_b  = (const float*)d_in[4];
    const float* rel_bias= (const float*)d_in[5];
    const float* norm1_g = (const float*)d_in[6];
    const float* norm1_b = (const float*)d_in[7];
    const float* norm2_g = (const float*)d_in[8];
    const float* norm2_b = (const float*)d_in[9];
    const float* fc1_w   = (const float*)d_in[10];
    const float* fc1_b   = (const float*)d_in[11];
    const float* fc2_w   = (const float*)d_in[12];
    const float* fc2_b   = (const float*)d_in[13];

    float *biasT;
    __half *xt, *x1, *xw, *qkv, *attout, *h, *wt_qkv, *wt_proj, *wt_fc1, *wt_fc2;
    cudaGetSymbolAddress((void**)&xt, g_xt);
    cudaGetSymbolAddress((void**)&xw, g_xw);
    cudaGetSymbolAddress((void**)&qkv, g_qkv);
    cudaGetSymbolAddress((void**)&attout, g_attout);
    cudaGetSymbolAddress((void**)&x1, g_x1);
    cudaGetSymbolAddress((void**)&h, g_h);
    cudaGetSymbolAddress((void**)&biasT, g_biasT);
    cudaGetSymbolAddress((void**)&wt_qkv, g_wt_qkv);
    cudaGetSymbolAddress((void**)&wt_proj, g_wt_proj);
    cudaGetSymbolAddress((void**)&wt_fc1, g_wt_fc1);
    cudaGetSymbolAddress((void**)&wt_fc2, g_wt_fc2);

    cudaFuncSetAttribute(hgemm<0>, cudaFuncAttributeMaxDynamicSharedMemorySize, HG_SMEM);
    cudaFuncSetAttribute(hgemm<1>, cudaFuncAttributeMaxDynamicSharedMemorySize, HG_SMEM);
    cudaFuncSetAttribute(hgemm<3>, cudaFuncAttributeMaxDynamicSharedMemorySize, HG_SMEM);
    cudaFuncSetAttribute(hgemm<4>, cudaFuncAttributeMaxDynamicSharedMemorySize, HG_SMEM);
    cudaFuncSetAttribute(fuse_in_ln, cudaFuncAttributeMaxDynamicSharedMemorySize, 384 * 33 * 4);

    // 0. weight transposes + bias transpose (one launch)
    transpose_w4<<<dim3(48, 48, 5), dim3(32, 8)>>>(qkv_w, proj_w, fc1_w, fc2_w, rel_bias,
                                                   wt_qkv, wt_proj, wt_fc1, wt_fc2, biasT);
    // 1+2. fused BCHW->token transpose + LN1 + shift + window partition
    fuse_in_ln<<<dim3(128, 32), 256, 384 * 33 * 4>>>(x, norm1_g, norm1_b, xt, xw);
    // 3. QKV projection -> half
    hgemm<0><<<dim3(QKV_N / 128, NTOK / 128), 256, HG_SMEM>>>(xw, wt_qkv, qkv_b, nullptr, qkv,
                                                              NTOK, QKV_N, DIM);
    // 4. windowed attention (fp16 mma, register softmax) -> half
    attn_mma<<<2048 * HEADS, 128>>>(qkv, biasT, attout);
    // 5. output projection + fused window-reverse/unshift + residual(xt,half) -> x1 (half)
    hgemm<3><<<dim3(DIM / 128, NTOK / 128), 256, HG_SMEM>>>(attout, wt_proj, proj_b, xt, x1,
                                                            NTOK, DIM, DIM);
    // 6. LN2 (half in, vectorized) -> fp16
    ln_kernel<<<NTOK / 8, 256>>>(x1, norm2_g, norm2_b, xw);
    // 7. FC1 + GELU (tanh approx) -> fp16
    hgemm<1><<<dim3(MLP_HIDDEN / 128, NTOK / 128), 256, HG_SMEM>>>(xw, wt_fc1, fc1_b, nullptr, h,
                                                                   NTOK, MLP_HIDDEN, DIM);
    // 8. FC2 + residual(x1,half) -> d_out in BCHW directly (fused transpose)
    hgemm<4><<<dim3(DIM / 128, NTOK / 128), 256, HG_SMEM>>>(h, wt_fc2, fc2_b, x1, d_out,
                                                            NTOK, DIM, MLP_HIDDEN);
}

// round 16
// speedup vs baseline: 1.0167x; 1.0167x over previous
#include <cuda_runtime.h>
#include <cuda_fp16.h>
#include <cstdint>
#include <math.h>

#define DIM 384
#define HEADS 12
#define HEAD_DIM 32
#define NTOK 131072          // 32*64*64 tokens
#define QKV_N 1152
#define MLP_HIDDEN 1536
#define ATT_SCALE 0.17677669529663687f   // 32^-0.5

// ---------------- scratch (static device globals; no allocations) -------------
__device__ __half g_xt[NTOK * DIM];           // token-major input (shortcut, half)
__device__ __half g_xw[NTOK * DIM];           // LN output (GEMM A input)
__device__ __half g_qkv[NTOK * QKV_N];        // qkv projections (half)
__device__ __half g_attout[NTOK * DIM];       // attention output (GEMM A input)
__device__ __half g_x1[NTOK * DIM];           // post-attention residual (half)
__device__ __half g_h[NTOK * MLP_HIDDEN];     // MLP hidden (GEMM A input)
__device__ float  g_biasT[HEADS * 225];       // rel_bias transposed per head
// transposed (N,K) weights in fp16
__device__ __half g_wt_qkv[QKV_N * DIM];
__device__ __half g_wt_proj[DIM * DIM];
__device__ __half g_wt_fc1[MLP_HIDDEN * DIM];
__device__ __half g_wt_fc2[DIM * MLP_HIDDEN];

// ---------------- mma / ldmatrix helpers --------------------------------------
#define LDSM_X4(r0, r1, r2, r3, addr) \
    asm volatile("ldmatrix.sync.aligned.m8n8.x4.shared.b16 {%0,%1,%2,%3}, [%4];" \
                 : "=r"(r0), "=r"(r1), "=r"(r2), "=r"(r3) : "r"(addr))
#define LDSM_X4_T(r0, r1, r2, r3, addr) \
    asm volatile("ldmatrix.sync.aligned.m8n8.x4.trans.shared.b16 {%0,%1,%2,%3}, [%4];" \
                 : "=r"(r0), "=r"(r1), "=r"(r2), "=r"(r3) : "r"(addr))
#define MMA16816(d, a0, a1, a2, a3, b0, b1) \
    asm volatile("mma.sync.aligned.m16n8k16.row.col.f32.f16.f16.f32 " \
                 "{%0,%1,%2,%3}, {%4,%5,%6,%7}, {%8,%9}, {%0,%1,%2,%3};" \
                 : "+f"((d)[0]), "+f"((d)[1]), "+f"((d)[2]), "+f"((d)[3]) \
                 : "r"(a0), "r"(a1), "r"(a2), "r"(a3), "r"(b0), "r"(b1))

// fast GELU: 0.5x(1+tanh(sqrt(2/pi)(x+0.044715x^3))) with MUFU.TANH
__device__ __forceinline__ float gelu_fast(float u) {
    float t;
    float a = 0.7978845608028654f * (u + 0.044715f * u * u * u);
    asm("tanh.approx.f32 %0, %1;" : "=f"(t) : "f"(a));
    return 0.5f * u * (1.0f + t);
}

// ---------------- rel_bias transpose: [225][12] -> [12][225] ------------------
__global__ void prep_bias(const float* __restrict__ rel_bias, float* __restrict__ biasT) {
    int i = blockIdx.x * blockDim.x + threadIdx.x;
    if (i < 225 * HEADS) {
        int idx = i / HEADS, h = i - idx * HEADS;
        biasT[h * 225 + idx] = rel_bias[i];
    }
}

// ---------------- fused BCHW->token transpose + LN1 + shift + window scatter --
__global__ void fuse_in_ln(const float* __restrict__ x,
                           const float* __restrict__ gamma,
                           const float* __restrict__ beta,
                           __half* __restrict__ xt, __half* __restrict__ xw) {
    extern __shared__ float tile[];   // [384][33]
    int b = blockIdx.y;
    int p0 = blockIdx.x * 32;
    const float* xb = x + (size_t)b * DIM * 4096;
    int tx = threadIdx.x & 31;
    int ty = threadIdx.x >> 5;   // warp id, 8 warps

    for (int c = ty; c < DIM; c += 8)
        tile[c * 33 + tx] = xb[(size_t)c * 4096 + p0 + tx];
    __syncthreads();

    int lane = tx;
#pragma unroll
    for (int ti = 0; ti < 4; ti++) {
        int t = ty * 4 + ti;                 // 0..31
        int hw = p0 + t;
        float vals[12];
        float s = 0.f;
#pragma unroll
        for (int k = 0; k < 12; k++) {
            vals[k] = tile[(lane + k * 32) * 33 + t];
            s += vals[k];
        }
#pragma unroll
        for (int o = 16; o; o >>= 1) s += __shfl_xor_sync(0xffffffffu, s, o);
        float mu = s * (1.f / 384.f);
        float vv = 0.f;
#pragma unroll
        for (int k = 0; k < 12; k++) { float d = vals[k] - mu; vv += d * d; }
#pragma unroll
        for (int o = 16; o; o >>= 1) vv += __shfl_xor_sync(0xffffffffu, vv, o);
        float rstd = rsqrtf(vv * (1.f / 384.f) + 1e-5f);

        __half* xtr = xt + ((size_t)b * 4096 + hw) * DIM;
        int hs = hw >> 6, ws = hw & 63;
        int h = (hs + 60) & 63;   // unshift
        int w = (ws + 60) & 63;
        int drow = b * 4096 + ((h >> 3) * 8 + (w >> 3)) * 64 + ((h & 7) * 8 + (w & 7));
        __half* xwr = xw + (size_t)drow * DIM;
#pragma unroll
        for (int k = 0; k < 12; k++) {
            int c = lane + k * 32;
            xtr[c] = __float2half_rn(vals[k]);
            xwr[c] = __float2half_rn((vals[k] - mu) * rstd * gamma[c] + beta[c]);
        }
    }
}

// ---------------- all 4 weight transposes in ONE launch -----------------------
__global__ void transpose_w4(const float* __restrict__ qkv_w, const float* __restrict__ proj_w,
                             const float* __restrict__ fc1_w, const float* __restrict__ fc2_w,
                             __half* __restrict__ wt_qkv, __half* __restrict__ wt_proj,
                             __half* __restrict__ wt_fc1, __half* __restrict__ wt_fc2) {
    __shared__ float tile[32][33];
    int z = blockIdx.z;
    const float* W;
    __half* Wt;
    int K, N;
    if (z == 0)      { W = qkv_w;  Wt = wt_qkv;  K = DIM;        N = QKV_N; }
    else if (z == 1) { W = proj_w; Wt = wt_proj; K = DIM;        N = DIM; }
    else if (z == 2) { W = fc1_w;  Wt = wt_fc1;  K = DIM;        N = MLP_HIDDEN; }
    else             { W = fc2_w;  Wt = wt_fc2;  K = MLP_HIDDEN; N = DIM; }
    int n0 = blockIdx.x * 32;
    int k0 = blockIdx.y * 32;
    if (n0 >= N || k0 >= K) return;
    int tx = threadIdx.x, ty = threadIdx.y;
#pragma unroll
    for (int i = 0; i < 32; i += 8)
        tile[ty + i][tx] = W[(size_t)(k0 + ty + i) * N + n0 + tx];
    __syncthreads();
#pragma unroll
    for (int i = 0; i < 32; i += 8)
        Wt[(size_t)(n0 + ty + i) * K + k0 + tx] = __float2half_rn(tile[tx][ty + i]);
}

// ---------------- LayerNorm (token-order half in/out, vectorized) -------------
__global__ void ln_kernel(const __half* __restrict__ src,
                          const float* __restrict__ gamma,
                          const float* __restrict__ beta,
                          __half* __restrict__ dst) {
    int warp = (blockIdx.x * blockDim.x + threadIdx.x) >> 5;
    int lane = threadIdx.x & 31;
    if (warp >= NTOK) return;

    const __half2* row2 = (const __half2*)(src + (size_t)warp * DIM);
    float2 v[6];
    float s = 0.f;
#pragma unroll
    for (int k = 0; k < 6; k++) {
        v[k] = __half22float2(row2[lane + k * 32]);
        s += v[k].x + v[k].y;
    }
#pragma unroll
    for (int o = 16; o; o >>= 1) s += __shfl_xor_sync(0xffffffffu, s, o);
    float mu = s * (1.f / 384.f);
    float vv = 0.f;
#pragma unroll
    for (int k = 0; k < 6; k++) {
        float d0 = v[k].x - mu, d1 = v[k].y - mu;
        vv += d0 * d0 + d1 * d1;
    }
#pragma unroll
    for (int o = 16; o; o >>= 1) vv += __shfl_xor_sync(0xffffffffu, vv, o);
    float rstd = rsqrtf(vv * (1.f / 384.f) + 1e-5f);

    __half2* orow = (__half2*)(dst + (size_t)warp * DIM);
#pragma unroll
    for (int k = 0; k < 6; k++) {
        int c = (lane + k * 32) * 2;
        float o0 = (v[k].x - mu) * rstd * gamma[c] + beta[c];
        float o1 = (v[k].y - mu) * rstd * gamma[c + 1] + beta[c + 1];
        orow[lane + k * 32] = __floats2half2_rn(o0, o1);
    }
}

// ---------------- fused windowed attention (fp16 mma) ------------------------
__device__ __forceinline__ int region64(int v) { return v < 56 ? 0 : (v < 60 ? 1 : 2); }

__device__ __forceinline__ unsigned pkh2(float a, float b) {
    __half2 h = __floats2half2_rn(a, b);
    return *(unsigned*)&h;
}

#define ASTRIDE 40   // halfs per row: conflict-free for ldmatrix

__global__ __launch_bounds__(128) void attn_mma(const __half* __restrict__ qkv,
                                                const float* __restrict__ biasT,
                                                __half* __restrict__ out) {
    __shared__ __half Qs[64 * ASTRIDE];
    __shared__ __half Ks[64 * ASTRIDE];
    __shared__ __half Vs[64 * ASTRIDE];
    __shared__ float sbias[225];

    int blk = blockIdx.x;
    int win = blk / HEADS;
    int head = blk - win * HEADS;
    int tid = threadIdx.x;
    int lane = tid & 31, warp = tid >> 5;
    int grp = lane >> 2, lig = lane & 3;

    if (tid < 113) {
        sbias[tid] = biasT[head * 225 + tid];
        if (tid + 113 < 225) sbias[tid + 113] = biasT[head * 225 + tid + 113];
    }

    {   // stage Q,K,V via cp.async (16B each, all aligned)
        int n = tid >> 1;
        int c0 = (tid & 1) << 4;
        const __half* rowp = qkv + (size_t)(win * 64 + n) * QKV_N + head * HEAD_DIM + c0;
        unsigned q0 = (unsigned)__cvta_generic_to_shared(&Qs[n * ASTRIDE + c0]);
        unsigned k0 = (unsigned)__cvta_generic_to_shared(&Ks[n * ASTRIDE + c0]);
        unsigned v0 = (unsigned)__cvta_generic_to_shared(&Vs[n * ASTRIDE + c0]);
        asm volatile("cp.async.cg.shared.global [%0], [%1], 16;\n" :: "r"(q0), "l"(rowp));
        asm volatile("cp.async.cg.shared.global [%0], [%1], 16;\n" :: "r"(q0 + 16), "l"(rowp + 8));
        asm volatile("cp.async.cg.shared.global [%0], [%1], 16;\n" :: "r"(k0), "l"(rowp + DIM));
        asm volatile("cp.async.cg.shared.global [%0], [%1], 16;\n" :: "r"(k0 + 16), "l"(rowp + DIM + 8));
        asm volatile("cp.async.cg.shared.global [%0], [%1], 16;\n" :: "r"(v0), "l"(rowp + 2 * DIM));
        asm volatile("cp.async.cg.shared.global [%0], [%1], 16;\n" :: "r"(v0 + 16), "l"(rowp + 2 * DIM + 8));
        asm volatile("cp.async.commit_group;\n");
    }
    asm volatile("cp.async.wait_group 0;\n" ::: "memory");
    __syncthreads();

    const unsigned qb = (unsigned)__cvta_generic_to_shared(Qs);
    const unsigned kb = (unsigned)__cvta_generic_to_shared(Ks);
    const unsigned vb = (unsigned)__cvta_generic_to_shared(Vs);
    const int g = lane >> 3, j = lane & 7;

    unsigned qa[2][4];
#pragma unroll
    for (int kc = 0; kc < 2; kc++) {
        int row = warp * 16 + (g & 1) * 8 + j;
        int col = kc * 16 + (g >> 1) * 8;
        LDSM_X4(qa[kc][0], qa[kc][1], qa[kc][2], qa[kc][3],
                qb + (unsigned)((row * ASTRIDE + col) * 2));
    }

    float sacc[8][4];
#pragma unroll
    for (int nt = 0; nt < 8; nt++)
#pragma unroll
        for (int i = 0; i < 4; i++) sacc[nt][i] = 0.f;

#pragma unroll
    for (int kc = 0; kc < 2; kc++) {
#pragma unroll
        for (int p = 0; p < 4; p++) {
            unsigned kf[4];
            int row = p * 16 + (g >> 1) * 8 + j;
            int col = kc * 16 + (g & 1) * 8;
            LDSM_X4(kf[0], kf[1], kf[2], kf[3],
                    kb + (unsigned)((row * ASTRIDE + col) * 2));
            MMA16816(sacc[2 * p],     qa[kc][0], qa[kc][1], qa[kc][2], qa[kc][3], kf[0], kf[1]);
            MMA16816(sacc[2 * p + 1], qa[kc][0], qa[kc][1], qa[kc][2], qa[kc][3], kf[2], kf[3]);
        }
    }

    int win_img = win & 63;
    int wy = win_img >> 3, wx = win_img & 7;
    bool masked = (wy == 7) || (wx == 7);
    int r_lo = warp * 16 + grp, r_hi = r_lo + 8;
    int ry_lo = r_lo >> 3, rx = r_lo & 7;
    int ry_hi = r_hi >> 3;
    int reg_lo = 0, reg_hi = 0;
    if (masked) {
        reg_lo = region64(wy * 8 + ry_lo) * 3 + region64(wx * 8 + rx);
        reg_hi = region64(wy * 8 + ry_hi) * 3 + region64(wx * 8 + rx);
    }

    float mx_lo = -1e30f, mx_hi = -1e30f;
#pragma unroll
    for (int nt = 0; nt < 8; nt++) {
#pragma unroll
        for (int jj = 0; jj < 2; jj++) {
            int c = nt * 8 + 2 * lig + jj;
            int cy = c >> 3, cx = c & 7;
            float blo = sbias[(ry_lo - cy + 7) * 15 + (rx - cx + 7)];
            float bhi = sbias[(ry_hi - cy + 7) * 15 + (rx - cx + 7)];
            float mlo = 0.f, mhi = 0.f;
            if (masked) {
                int regc = region64(wy * 8 + cy) * 3 + region64(wx * 8 + cx);
                mlo = (reg_lo != regc) ? -10.f : 0.f;
                mhi = (reg_hi != regc) ? -10.f : 0.f;
            }
            float vlo = sacc[nt][jj] * ATT_SCALE + blo + mlo;
            float vhi = sacc[nt][2 + jj] * ATT_SCALE + bhi + mhi;
            sacc[nt][jj] = vlo;
            sacc[nt][2 + jj] = vhi;
            mx_lo = fmaxf(mx_lo, vlo);
            mx_hi = fmaxf(mx_hi, vhi);
        }
    }
    mx_lo = fmaxf(mx_lo, __shfl_xor_sync(0xffffffffu, mx_lo, 1));
    mx_lo = fmaxf(mx_lo, __shfl_xor_sync(0xffffffffu, mx_lo, 2));
    mx_hi = fmaxf(mx_hi, __shfl_xor_sync(0xffffffffu, mx_hi, 1));
    mx_hi = fmaxf(mx_hi, __shfl_xor_sync(0xffffffffu, mx_hi, 2));

    float sm_lo = 0.f, sm_hi = 0.f;
#pragma unroll
    for (int nt = 0; nt < 8; nt++) {
#pragma unroll
        for (int jj = 0; jj < 2; jj++) {
            float elo = __expf(sacc[nt][jj] - mx_lo);
            float ehi = __expf(sacc[nt][2 + jj] - mx_hi);
            sacc[nt][jj] = elo;
            sacc[nt][2 + jj] = ehi;
            sm_lo += elo;
            sm_hi += ehi;
        }
    }
    sm_lo += __shfl_xor_sync(0xffffffffu, sm_lo, 1);
    sm_lo += __shfl_xor_sync(0xffffffffu, sm_lo, 2);
    sm_hi += __shfl_xor_sync(0xffffffffu, sm_hi, 1);
    sm_hi += __shfl_xor_sync(0xffffffffu, sm_hi, 2);
    float inv_lo = 1.f / sm_lo, inv_hi = 1.f / sm_hi;

    float oacc[4][4];
#pragma unroll
    for (int nt = 0; nt < 4; nt++)
#pragma unroll
        for (int i = 0; i < 4; i++) oacc[nt][i] = 0.f;

#pragma unroll
    for (int kc = 0; kc < 4; kc++) {
        unsigned pa[4];
        pa[0] = pkh2(sacc[2 * kc][0] * inv_lo,     sacc[2 * kc][1] * inv_lo);
        pa[1] = pkh2(sacc[2 * kc][2] * inv_hi,     sacc[2 * kc][3] * inv_hi);
        pa[2] = pkh2(sacc[2 * kc + 1][0] * inv_lo, sacc[2 * kc + 1][1] * inv_lo);
        pa[3] = pkh2(sacc[2 * kc + 1][2] * inv_hi, sacc[2 * kc + 1][3] * inv_hi);
#pragma unroll
        for (int q = 0; q < 2; q++) {
            unsigned vf[4];
            int row = kc * 16 + (g & 1) * 8 + j;
            int col = q * 16 + (g >> 1) * 8;
            LDSM_X4_T(vf[0], vf[1], vf[2], vf[3],
                      vb + (unsigned)((row * ASTRIDE + col) * 2));
            MMA16816(oacc[2 * q],     pa[0], pa[1], pa[2], pa[3], vf[0], vf[1]);
            MMA16816(oacc[2 * q + 1], pa[0], pa[1], pa[2], pa[3], vf[2], vf[3]);
        }
    }

#pragma unroll
    for (int nt = 0; nt < 4; nt++) {
        int col = head * HEAD_DIM + nt * 8 + 2 * lig;
        __half2 lo = __floats2half2_rn(oacc[nt][0], oacc[nt][1]);
        __half2 hi = __floats2half2_rn(oacc[nt][2], oacc[nt][3]);
        *(__half2*)&out[(size_t)(win * 64 + r_lo) * DIM + col] = lo;
        *(__half2*)&out[(size_t)(win * 64 + r_hi) * DIM + col] = hi;
    }
}

// ================= fp16 tensor-core GEMM (m16n8k16 mma.sync) =================
// MODE 0: half out. MODE 1: GELU, half out.
// MODE 3: window-reverse+unshift + residual(half), half out (token order).
// MODE 4: +res(half), write BCHW (transposed, smem-staged), float out = d_out.
#define BKH 64
#define SA 72
#define SB 72
#define STAGES 3
#define HG_SMEM (STAGES * 128 * (SA + SB) * 2)

template <int MODE>
__global__ __launch_bounds__(256, 2) void hgemm(const __half* __restrict__ A,
                                                const __half* __restrict__ Bt,
                                                const float* __restrict__ bias,
                                                const __half* __restrict__ res,
                                                void* __restrict__ Cout,
                                                int M, int N, int K) {
    extern __shared__ __half dsm[];
    __half* Asb = dsm;                          // STAGES * 128*SA
    __half* Bsb = dsm + STAGES * 128 * SA;      // STAGES * 128*SB

    const int tid = threadIdx.x;
    const int lane = tid & 31;
    const int wid = tid >> 5;
    const int grp = lane >> 2;
    const int lig = lane & 3;
    const int g = lane >> 3;
    const int j = lane & 7;
    const int wm = wid & 3;
    const int wn = wid >> 2;
    const int bm = blockIdx.y * 128;
    const int bn = blockIdx.x * 128;

    const int l_r = tid >> 3;           // 0..31
    const int l_c = (tid & 7) << 3;     // 0,8,...,56 halfs

    float acc[2][8][4];
#pragma unroll
    for (int mt = 0; mt < 2; mt++)
#pragma unroll
        for (int nt = 0; nt < 8; nt++)
#pragma unroll
            for (int i = 0; i < 4; i++) acc[mt][nt][i] = 0.f;

    const int T = K / BKH;

    auto issue = [&](int t) {
        if (t < T) {
            int kt = t * BKH;
            int buf = t % STAGES;
            __half* Ad = Asb + buf * 128 * SA;
            __half* Bd = Bsb + buf * 128 * SB;
#pragma unroll
            for (int i = 0; i < 4; i++) {
                int r = l_r + 32 * i;
                const __half* gp = A + (size_t)(bm + r) * K + kt + l_c;
                unsigned s = (unsigned)__cvta_generic_to_shared(&Ad[r * SA + l_c]);
                asm volatile("cp.async.cg.shared.global [%0], [%1], 16;\n" :: "r"(s), "l"(gp));
            }
#pragma unroll
            for (int i = 0; i < 4; i++) {
                int r = l_r + 32 * i;
                const __half* gp = Bt + (size_t)(bn + r) * K + kt + l_c;
                unsigned s = (unsigned)__cvta_generic_to_shared(&Bd[r * SB + l_c]);
                asm volatile("cp.async.cg.shared.global [%0], [%1], 16;\n" :: "r"(s), "l"(gp));
            }
        }
        asm volatile("cp.async.commit_group;\n");
    };

    issue(0);
    issue(1);

    for (int t = 0; t < T; t++) {
        asm volatile("cp.async.wait_group 1;\n" ::: "memory");
        __syncthreads();

        int buf = t % STAGES;
        const unsigned abx = (unsigned)__cvta_generic_to_shared(Asb + buf * 128 * SA);
        const unsigned bbx = (unsigned)__cvta_generic_to_shared(Bsb + buf * 128 * SB);

        unsigned af[2][4], bf[4][4];
        auto ldfrag = [&](int kk) {
            int colA = kk * 16 + (g >> 1) * 8;
#pragma unroll
            for (int mt = 0; mt < 2; mt++) {
                int row = wm * 32 + mt * 16 + (g & 1) * 8 + j;
                LDSM_X4(af[mt][0], af[mt][1], af[mt][2], af[mt][3],
                        abx + (unsigned)((row * SA + colA) * 2));
            }
#pragma unroll
            for (int p = 0; p < 4; p++) {
                int row = wn * 64 + p * 16 + (g & 1) * 8 + j;
                LDSM_X4(bf[p][0], bf[p][1], bf[p][2], bf[p][3],
                        bbx + (unsigned)((row * SB + colA) * 2));
            }
        };

        ldfrag(0);
        issue(t + 2);

#pragma unroll
        for (int kk = 0; kk < 4; kk++) {
#pragma unroll
            for (int mt = 0; mt < 2; mt++)
#pragma unroll
                for (int p = 0; p < 4; p++) {
                    MMA16816(acc[mt][2 * p],     af[mt][0], af[mt][1], af[mt][2], af[mt][3],
                             bf[p][0], bf[p][2]);
                    MMA16816(acc[mt][2 * p + 1], af[mt][0], af[mt][1], af[mt][2], af[mt][3],
                             bf[p][1], bf[p][3]);
                }
            if (kk < 3) ldfrag(kk + 1);
        }
    }
    __syncthreads();

    if (MODE == 4) {
        // FC2: bias + residual, then transposed write to BCHW via smem staging.
        float* st = reinterpret_cast<float*>(Asb);  // 128x33 floats
        int b = bm >> 12;
        int hw0 = bm & 4095;
        float* ybase = (float*)Cout + ((size_t)b * DIM + bn) * 4096 + hw0;
#pragma unroll
        for (int c = 0; c < 4; c++) {
            if ((c >> 1) == wn) {
                int nt0 = (c & 1) * 4;
#pragma unroll
                for (int mt = 0; mt < 2; mt++)
#pragma unroll
                    for (int hf = 0; hf < 2; hf++) {
                        int ml = wm * 32 + mt * 16 + grp + hf * 8;
                        const __half* rr = res + (size_t)(bm + ml) * DIM + bn + c * 32;
#pragma unroll
                        for (int q = 0; q < 4; q++) {
                            int nt = nt0 + q;
                            int nl = q * 8 + lig * 2;
                            int ng = bn + c * 32 + nl;
                            __half2 rv = *(const __half2*)(rr + nl);
                            st[ml * 33 + nl]     = acc[mt][nt][hf * 2 + 0] + bias[ng] + __half2float(rv.x);
                            st[ml * 33 + nl + 1] = acc[mt][nt][hf * 2 + 1] + bias[ng + 1] + __half2float(rv.y);
                        }
                    }
            }
            __syncthreads();
            {
                int nl = tid >> 3;
                int m0 = (tid & 7) << 4;
                float* dst = ybase + (size_t)(c * 32 + nl) * 4096 + m0;
#pragma unroll
                for (int i = 0; i < 4; i++) {
                    float4 o;
                    o.x = st[(m0 + 4 * i + 0) * 33 + nl];
                    o.y = st[(m0 + 4 * i + 1) * 33 + nl];
                    o.z = st[(m0 + 4 * i + 2) * 33 + nl];
                    o.w = st[(m0 + 4 * i + 3) * 33 + nl];
                    *(float4*)(dst + 4 * i) = o;
                }
            }
            __syncthreads();
        }
        return;
    }

#pragma unroll
    for (int mt = 0; mt < 2; mt++) {
#pragma unroll
        for (int half_ = 0; half_ < 2; half_++) {
            int m = bm + wm * 32 + mt * 16 + grp + half_ * 8;
            size_t crow;
            size_t rrow = 0;
            if (MODE == 3) {
                int b = m >> 12, win = (m >> 6) & 63, pos = m & 63;
                int wy = win >> 3, wx = win & 7, iy = pos >> 3, ix = pos & 7;
                int h = (wy * 8 + iy + 4) & 63;
                int w = (wx * 8 + ix + 4) & 63;
                size_t tk = (size_t)b * 4096 + h * 64 + w;
                crow = tk * N;
                rrow = tk * DIM;
            } else {
                crow = (size_t)m * N;
            }
#pragma unroll
            for (int nt = 0; nt < 8; nt++) {
                int n = bn + wn * 64 + nt * 8 + lig * 2;
                float v0 = acc[mt][nt][half_ * 2 + 0] + bias[n];
                float v1 = acc[mt][nt][half_ * 2 + 1] + bias[n + 1];
                if (MODE == 0) {
                    *(__half2*)((__half*)Cout + crow + n) = __floats2half2_rn(v0, v1);
                } else if (MODE == 1) {
                    v0 = gelu_fast(v0);
                    v1 = gelu_fast(v1);
                    *(__half2*)((__half*)Cout + crow + n) = __floats2half2_rn(v0, v1);
                } else {  // MODE 3: + residual(half), half out
                    __half2 rv = *(const __half2*)(res + rrow + n);
                    v0 += __half2float(rv.x);
                    v1 += __half2float(rv.y);
                    *(__half2*)((__half*)Cout + crow + n) = __floats2half2_rn(v0, v1);
                }
            }
        }
    }
}

// ---------------- launcher -----------------------------------------------------
extern "C" void kernel_launch(void* const* d_in, const int* in_sizes, int n_in,
                              void* d_out, int out_size) {
    const float* x       = (const float*)d_in[0];
    const float* qkv_w   = (const float*)d_in[1];
    const float* qkv_b   = (const float*)d_in[2];
    const float* proj_w  = (const float*)d_in[3];
    const float* proj_b  = (const float*)d_in[4];
    const float* rel_bias= (const float*)d_in[5];
    const float* norm1_g = (const float*)d_in[6];
    const float* norm1_b = (const float*)d_in[7];
    const float* norm2_g = (const float*)d_in[8];
    const float* norm2_b = (const float*)d_in[9];
    const float* fc1_w   = (const float*)d_in[10];
    const float* fc1_b   = (const float*)d_in[11];
    const float* fc2_w   = (const float*)d_in[12];
    const float* fc2_b   = (const float*)d_in[13];

    float *biasT;
    __half *xt, *x1, *xw, *qkv, *attout, *h, *wt_qkv, *wt_proj, *wt_fc1, *wt_fc2;
    cudaGetSymbolAddress((void**)&xt, g_xt);
    cudaGetSymbolAddress((void**)&xw, g_xw);
    cudaGetSymbolAddress((void**)&qkv, g_qkv);
    cudaGetSymbolAddress((void**)&attout, g_attout);
    cudaGetSymbolAddress((void**)&x1, g_x1);
    cudaGetSymbolAddress((void**)&h, g_h);
    cudaGetSymbolAddress((void**)&biasT, g_biasT);
    cudaGetSymbolAddress((void**)&wt_qkv, g_wt_qkv);
    cudaGetSymbolAddress((void**)&wt_proj, g_wt_proj);
    cudaGetSymbolAddress((void**)&wt_fc1, g_wt_fc1);
    cudaGetSymbolAddress((void**)&wt_fc2, g_wt_fc2);

    cudaFuncSetAttribute(hgemm<0>, cudaFuncAttributeMaxDynamicSharedMemorySize, HG_SMEM);
    cudaFuncSetAttribute(hgemm<1>, cudaFuncAttributeMaxDynamicSharedMemorySize, HG_SMEM);
    cudaFuncSetAttribute(hgemm<3>, cudaFuncAttributeMaxDynamicSharedMemorySize, HG_SMEM);
    cudaFuncSetAttribute(hgemm<4>, cudaFuncAttributeMaxDynamicSharedMemorySize, HG_SMEM);
    cudaFuncSetAttribute(fuse_in_ln, cudaFuncAttributeMaxDynamicSharedMemorySize, 384 * 33 * 4);

    // 0. weight transposes + bias transpose
    transpose_w4<<<dim3(48, 48, 4), dim3(32, 8)>>>(qkv_w, proj_w, fc1_w, fc2_w,
                                                   wt_qkv, wt_proj, wt_fc1, wt_fc2);
    prep_bias<<<11, 256>>>(rel_bias, biasT);
    // 1+2. fused BCHW->token transpose + LN1 + shift + window partition
    fuse_in_ln<<<dim3(128, 32), 256, 384 * 33 * 4>>>(x, norm1_g, norm1_b, xt, xw);
    // 3. QKV projection -> half
    hgemm<0><<<dim3(QKV_N / 128, NTOK / 128), 256, HG_SMEM>>>(xw, wt_qkv, qkv_b, nullptr, qkv,
                                                              NTOK, QKV_N, DIM);
    // 4. windowed attention (fp16 mma, register softmax) -> half
    attn_mma<<<2048 * HEADS, 128>>>(qkv, biasT, attout);
    // 5. output projection + fused window-reverse/unshift + residual(xt,half) -> x1 (half)
    hgemm<3><<<dim3(DIM / 128, NTOK / 128), 256, HG_SMEM>>>(attout, wt_proj, proj_b, xt, x1,
                                                            NTOK, DIM, DIM);
    // 6. LN2 (half in, vectorized) -> fp16
    ln_kernel<<<NTOK / 8, 256>>>(x1, norm2_g, norm2_b, xw);
    // 7. FC1 + GELU (tanh approx) -> fp16
    hgemm<1><<<dim3(MLP_HIDDEN / 128, NTOK / 128), 256, HG_SMEM>>>(xw, wt_fc1, fc1_b, nullptr, h,
                                                                   NTOK, MLP_HIDDEN, DIM);
    // 8. FC2 + residual(x1,half) -> d_out in BCHW directly (fused transpose)
    hgemm<4><<<dim3(DIM / 128, NTOK / 128), 256, HG_SMEM>>>(h, wt_fc2, fc2_b, x1, d_out,
                                                            NTOK, DIM, MLP_HIDDEN);
}